// round 12
// baseline (speedup 1.0000x reference)
#include <cuda_runtime.h>
#include <cuda_bf16.h>
#include <cstdint>

// LinearSelfAttention, factored:
//   G  = H[:, :2048] @ H[:, :2048]^T   (mask == K-truncation; G symmetric)
//   T1 = P @ G ;  A2 = T1 @ Q ;  out = H + (A2 @ H) / 2048
// bf16 mma.sync + ldmatrix, SW128 smem, 128x128 tiles, 3-stage cp.async.
// G is split-K=2: partials [G0|G1] (each symmetric), consumed by step 2 as
// T1 = [P|P] @ [G0|G1]^T  (K=768) -- combine folded into the GEMM.

#define BATCH 16
#define D_REAL 257
#define N_REAL 2049
#define HSTR   (257L * 2049L)

#define DP 384      // padded d as M/N (mult of 128)
#define DK 320      // padded d as K   (mult of 64)
#define NP 2176     // padded n        (mult of 128)
#define NSTG 3
#define BK 64       // K per chunk = 128 B per row = SW128 atom
#define GLD 768     // row stride of [G0|G1] and [P|P]

__device__ __align__(256) __nv_bfloat16 g_Hb [BATCH * DP * NP];
__device__ __align__(256) __nv_bfloat16 g_HbT[BATCH * NP * DP];
__device__ __align__(256) __nv_bfloat16 g_Pb2[DP * GLD];          // [P|P]
__device__ __align__(256) __nv_bfloat16 g_QbT[DP * DK];
__device__ __align__(256) __nv_bfloat16 g_Gp [BATCH * DP * GLD];  // [G0|G1]
__device__ __align__(256) __nv_bfloat16 g_S1 [BATCH * DP * DP];
__device__ __align__(256) __nv_bfloat16 g_S2 [BATCH * DP * DP];

// ---------------------------------------------------------------- helpers

__device__ __forceinline__ uint32_t smem_u32(const void* p) {
    uint32_t a;
    asm("{ .reg .u64 t; cvta.to.shared.u64 t, %1; cvt.u32.u64 %0, t; }"
        : "=r"(a) : "l"(p));
    return a;
}

__device__ __forceinline__ void cp16s(uint32_t dst, const void* src) {
    asm volatile("cp.async.cg.shared.global [%0], [%1], 16;\n" :: "r"(dst), "l"(src));
}

#define SWZ(off) ((off) ^ (((off) >> 3) & 0x70))

__device__ __forceinline__ void ldm_x4(uint32_t* r, uint32_t addr) {
    asm volatile("ldmatrix.sync.aligned.m8n8.x4.shared.b16 {%0,%1,%2,%3}, [%4];"
                 : "=r"(r[0]), "=r"(r[1]), "=r"(r[2]), "=r"(r[3]) : "r"(addr));
}

__device__ __forceinline__ void mma16816(float* d, const uint32_t* a,
                                         uint32_t b0, uint32_t b1) {
    asm volatile(
        "mma.sync.aligned.m16n8k16.row.col.f32.bf16.bf16.f32 "
        "{%0,%1,%2,%3}, {%4,%5,%6,%7}, {%8,%9}, {%0,%1,%2,%3};"
        : "+f"(d[0]), "+f"(d[1]), "+f"(d[2]), "+f"(d[3])
        : "r"(a[0]), "r"(a[1]), "r"(a[2]), "r"(a[3]), "r"(b0), "r"(b1));
}

// ---------------------------------------------------------------- converts

__global__ void conv_H(const float* __restrict__ H,
                       __nv_bfloat16* __restrict__ Hb,
                       __nv_bfloat16* __restrict__ HbT)
{
    __shared__ float t[32][33];
    const int b  = blockIdx.z;
    const int n0 = blockIdx.x * 32;
    const int d0 = blockIdx.y * 32;
    const int tx = threadIdx.x, ty = threadIdx.y;
    const float* Hp = H + (long)b * HSTR;

    #pragma unroll
    for (int i = 0; i < 4; i++) {
        int d = d0 + ty + i * 8, n = n0 + tx;
        float v = 0.f;
        if (d < D_REAL && n < N_REAL) v = Hp[(long)d * N_REAL + n];
        t[ty + i * 8][tx] = v;
    }
    __syncthreads();
    __nv_bfloat16* Hbp  = Hb  + (long)b * DP * NP;
    __nv_bfloat16* HbTp = HbT + (long)b * NP * DP;
    #pragma unroll
    for (int i = 0; i < 4; i++) {
        int d = d0 + ty + i * 8, n = n0 + tx;
        Hbp[(long)d * NP + n] = __float2bfloat16(t[ty + i * 8][tx]);
    }
    #pragma unroll
    for (int i = 0; i < 4; i++) {
        int n = n0 + ty + i * 8, d = d0 + tx;
        HbTp[(long)n * DP + d] = __float2bfloat16(t[tx][ty + i * 8]);
    }
}

__global__ void conv_P2(const float* __restrict__ P, __nv_bfloat16* __restrict__ Pb2)
{
    int idx = blockIdx.x * blockDim.x + threadIdx.x;
    if (idx >= DP * GLD) return;
    int r = idx / GLD, c = idx % GLD;
    int k = (c >= DP) ? c - DP : c;
    Pb2[idx] = __float2bfloat16((r < D_REAL && k < D_REAL) ? P[r * D_REAL + k] : 0.f);
}

__global__ void conv_QT(const float* __restrict__ Q, __nv_bfloat16* __restrict__ QbT)
{
    int idx = blockIdx.x * blockDim.x + threadIdx.x;
    if (idx >= DP * DK) return;
    int n = idx / DK, k = idx % DK;
    QbT[idx] = __float2bfloat16((n < D_REAL && k < D_REAL) ? Q[k * D_REAL + n] : 0.f);
}

// ---------------------------------------------------------------- GEMM NT

// C[M,N] = scale * A[M,K] @ B[N,K]^T. 128x128 CTA tile, warp tile 64x32.
// SPLITK=1: blockIdx.y = mtile*2 + split; A/B advance split*1024 in k,
//           K=1024 per split, C columns shift by split*DP (ldc=GLD).
// EPI=0: bf16 to Cb (padded). EPI=1: fp32 out = Hadd + acc*scale, guarded.
template<int EPI, int SPLITK>
__global__ void __launch_bounds__(256, 2)
gemm_nt(const __nv_bfloat16* __restrict__ A,
        const __nv_bfloat16* __restrict__ B,
        __nv_bfloat16* __restrict__ Cb,
        float* __restrict__ Cf,
        const float* __restrict__ Hadd,
        int K, int lda, int ldb, int ldc,
        long sA, long sB, long sC, float scale)
{
    extern __shared__ __align__(1024) char dyn[];
    const int bz = blockIdx.z;
    A += (long)bz * sA;
    B += (long)bz * sB;

    int bm, cshift;
    if (SPLITK) {
        const int split = blockIdx.y & 1;
        bm = (blockIdx.y >> 1) * 128;
        cshift = split * DP;
        A += split * 1024;
        B += split * 1024;
    } else {
        bm = blockIdx.y * 128;
        cshift = 0;
    }
    const int bn = blockIdx.x * 128;
    const int tid  = threadIdx.x;
    const int lane = tid & 31;
    const int wid  = tid >> 5;
    const int g    = lane >> 2;
    const int tig  = lane & 3;
    const int wm   = (wid & 1) * 64;     // 2 warps over m
    const int wn   = (wid >> 1) * 32;    // 4 warps over n

    const uint32_t base = smem_u32(dyn);  // [NSTG][A:16KB | B:16KB]

    float acc[4][4][4];
    #pragma unroll
    for (int i = 0; i < 4; i++)
        #pragma unroll
        for (int j = 0; j < 4; j++)
            #pragma unroll
            for (int r = 0; r < 4; r++) acc[i][j][r] = 0.f;

    const uint32_t swx      = (uint32_t)((lane & 7) << 4);
    const uint32_t a_rowoff = (uint32_t)(wm + (lane & 15)) * 128;
    const uint32_t a_koff   = (uint32_t)((lane >> 4) * 16);
    const uint32_t b_rowoff = (uint32_t)(wn + (lane & 7) + ((lane >> 4) & 1) * 8) * 128;
    const uint32_t b_koff   = (uint32_t)(((lane >> 3) & 1) * 16);

    auto load_chunk = [&](int c) {
        const int st = c % NSTG;
        const uint32_t ab = base + st * 32768;
        const uint32_t bb = ab + 16384;
        const int k0 = c * BK;
        #pragma unroll
        for (int i = 0; i < 4; i++) {
            int ch  = tid + i * 256;
            int row = ch >> 3;
            int q   = ch & 7;
            uint32_t off = SWZ(row * 128 + q * 16);
            cp16s(ab + off, A + (long)(bm + row) * lda + k0 + q * 8);
            cp16s(bb + off, B + (long)(bn + row) * ldb + k0 + q * 8);
        }
        asm volatile("cp.async.commit_group;");
    };

    const int nk = K / BK;   // >= NSTG at every call site
    load_chunk(0);
    load_chunk(1);

    for (int kt = 0; kt < nk; kt++) {
        if (kt + 2 < nk) load_chunk(kt + 2);
        else asm volatile("cp.async.commit_group;");
        asm volatile("cp.async.wait_group %0;" :: "n"(NSTG - 1));
        __syncthreads();

        const uint32_t ab = base + (kt % NSTG) * 32768;
        const uint32_t bb = ab + 16384;

        #pragma unroll
        for (int kk = 0; kk < 4; kk++) {               // 4 x k16 per BK=64
            uint32_t af[4][4], bf[2][4];
            #pragma unroll
            for (int mi = 0; mi < 4; mi++)
                ldm_x4(af[mi], ab + a_rowoff + mi * 2048
                               + ((uint32_t)(kk * 32) + a_koff ^ swx));
            #pragma unroll
            for (int p = 0; p < 2; p++)
                ldm_x4(bf[p], bb + b_rowoff + p * 2048
                              + ((uint32_t)(kk * 32) + b_koff ^ swx));
            #pragma unroll
            for (int mi = 0; mi < 4; mi++)
                #pragma unroll
                for (int ni = 0; ni < 4; ni++)
                    mma16816(acc[mi][ni], af[mi],
                             bf[ni >> 1][(ni & 1) * 2], bf[ni >> 1][(ni & 1) * 2 + 1]);
        }
        __syncthreads();
    }

    if (EPI == 0) {
        __nv_bfloat16* Cp = Cb + (long)bz * sC;
        #pragma unroll
        for (int mi = 0; mi < 4; mi++) {
            int r0 = bm + wm + mi * 16 + g;
            #pragma unroll
            for (int ni = 0; ni < 4; ni++) {
                int c = cshift + bn + wn + ni * 8 + tig * 2;
                __nv_bfloat162 v01, v23;
                v01.x = __float2bfloat16(acc[mi][ni][0] * scale);
                v01.y = __float2bfloat16(acc[mi][ni][1] * scale);
                v23.x = __float2bfloat16(acc[mi][ni][2] * scale);
                v23.y = __float2bfloat16(acc[mi][ni][3] * scale);
                *(__nv_bfloat162*)&Cp[(long)r0 * ldc + c]       = v01;
                *(__nv_bfloat162*)&Cp[(long)(r0 + 8) * ldc + c] = v23;
            }
        }
    } else {
        const float* Hp = Hadd + (long)bz * HSTR;
        float*       Op = Cf   + (long)bz * HSTR;
        #pragma unroll
        for (int mi = 0; mi < 4; mi++) {
            int r0 = bm + wm + mi * 16 + g;
            #pragma unroll
            for (int ni = 0; ni < 4; ni++) {
                int c = bn + wn + ni * 8 + tig * 2;
                #pragma unroll
                for (int half = 0; half < 2; half++) {
                    int r = r0 + half * 8;
                    if (r < D_REAL) {
                        if (c < N_REAL) {
                            long idx = (long)r * N_REAL + c;
                            Op[idx] = Hp[idx] + acc[mi][ni][half * 2 + 0] * scale;
                        }
                        if (c + 1 < N_REAL) {
                            long idx = (long)r * N_REAL + c + 1;
                            Op[idx] = Hp[idx] + acc[mi][ni][half * 2 + 1] * scale;
                        }
                    }
                }
            }
        }
    }
}

// ---------------------------------------------------------------- launch

extern "C" void kernel_launch(void* const* d_in, const int* in_sizes, int n_in,
                              void* d_out, int out_size)
{
    const float* H = (const float*)d_in[0];
    const float* P = (const float*)d_in[1];
    const float* Q = (const float*)d_in[2];
    float* out = (float*)d_out;

    void *pHb, *pHbT, *pPb2, *pQbT, *pGp, *pS1, *pS2;
    cudaGetSymbolAddress(&pHb,  g_Hb);
    cudaGetSymbolAddress(&pHbT, g_HbT);
    cudaGetSymbolAddress(&pPb2, g_Pb2);
    cudaGetSymbolAddress(&pQbT, g_QbT);
    cudaGetSymbolAddress(&pGp,  g_Gp);
    cudaGetSymbolAddress(&pS1,  g_S1);
    cudaGetSymbolAddress(&pS2,  g_S2);
    __nv_bfloat16* Hb  = (__nv_bfloat16*)pHb;
    __nv_bfloat16* HbT = (__nv_bfloat16*)pHbT;
    __nv_bfloat16* Pb2 = (__nv_bfloat16*)pPb2;
    __nv_bfloat16* QbT = (__nv_bfloat16*)pQbT;
    __nv_bfloat16* Gp  = (__nv_bfloat16*)pGp;
    __nv_bfloat16* S1  = (__nv_bfloat16*)pS1;
    __nv_bfloat16* S2  = (__nv_bfloat16*)pS2;

    const long sHN = (long)DP * NP;
    const long sNT = (long)NP * DP;
    const long sDD = (long)DP * DP;
    const long sG  = (long)DP * GLD;

    conv_H <<<dim3(NP / 32, DP / 32, BATCH), dim3(32, 8)>>>(H, Hb, HbT);
    conv_P2<<<(DP * GLD + 255) / 256, 256>>>(P, Pb2);
    conv_QT<<<(DP * DK + 255) / 256, 256>>>(Q, QbT);

    const int smem = NSTG * 32768;   // 96 KB
    cudaFuncSetAttribute(gemm_nt<0, 0>, cudaFuncAttributeMaxDynamicSharedMemorySize, smem);
    cudaFuncSetAttribute(gemm_nt<0, 1>, cudaFuncAttributeMaxDynamicSharedMemorySize, smem);
    cudaFuncSetAttribute(gemm_nt<1, 0>, cudaFuncAttributeMaxDynamicSharedMemorySize, smem);

    dim3 blk(256);
    dim3 gG   (DP / 128, (DP / 128) * 2, BATCH);  // 3 x 6 x 16 = 288 (split-K=2)
    dim3 gSq  (DP / 128, DP / 128, BATCH);        // 3 x 3 x 16 = 144
    dim3 gWide(NP / 128, DP / 128, BATCH);        // 17 x 3 x 16 = 816

    // 1) [G0|G1] = H @ H^T over K halves 1024+1024  (mask == K-truncation)
    gemm_nt<0, 1><<<gG, blk, smem>>>(Hb, Hb, Gp, nullptr, nullptr,
                                     1024, NP, NP, GLD, sHN, sHN, sG, 1.f);
    // 2) T1 = [P|P] @ [G0|G1]^T  (K=768 performs the split-K combine)
    gemm_nt<0, 0><<<gSq, blk, smem>>>(Pb2, Gp, S2, nullptr, nullptr,
                                      GLD, GLD, GLD, DP, 0, sG, sDD, 1.f);
    // 3) A2 = T1 @ Q
    gemm_nt<0, 0><<<gSq, blk, smem>>>(S2, QbT, S1, nullptr, nullptr,
                                      DK, DP, DK, DP, sDD, 0, sDD, 1.f);
    // 4) out = H + (A2 @ H) / 2048
    gemm_nt<1, 0><<<gWide, blk, smem>>>(S1, HbT, nullptr, out, H,
                                        DK, DP, DP, 0, sDD, sNT, 0, 1.f / 2048.f);
}